// round 12
// baseline (speedup 1.0000x reference)
#include <cuda_runtime.h>
#include <cuda_fp16.h>
#include <math.h>
#include <stdint.h>

#define TT 512
#define BB 64
#define EE 300
#define HH 512
#define LL 5
#define TB (TT*BB)
#define G3 (3*HH)

// ---------------- scratch (static device globals; no allocation) ----------------
__device__ float  g_x[TB * EE];     // embedded inputs [T*B, 300]
__device__ float  g_xp[TB * G3];    // input projections for current layer [T*B, 1536]
__device__ float  g_h1[TB * HH];    // layer-0 hidden outputs (fp32, feeds gemm1)
__device__ float  g_h2[TB * HH];    // layer-1 hidden outputs (fp32, feeds pool)
__device__ __half g_hex[TB * HH];   // fp16 h exchange buffer (per-step slots)
__device__ int    g_flag[2][TT][4][32]; // per (layer, step, batch-group, cta) flags

__device__ __forceinline__ uint32_t cvt_tf32(float f) {
    uint32_t u;
    asm("cvt.rna.tf32.f32 %0, %1;" : "=r"(u) : "f"(f));
    return u;
}
__device__ __forceinline__ uint32_t pack_f16x2(float a, float b) {
    uint32_t u;
    asm("cvt.rn.f16x2.f32 %0, %2, %1;" : "=r"(u) : "f"(a), "f"(b));
    return u;
}

// ---------------- flag reset ----------------
__global__ void zero_bar_kernel() {
    int i = blockIdx.x * blockDim.x + threadIdx.x;
    ((int*)g_flag)[i] = 0;     // grid sized exactly: 2*512*4*32 = 131072
}

// ---------------- embedding gather ----------------
__global__ void embed_kernel(const int* __restrict__ texts,
                             const float* __restrict__ emb) {
    int row = blockIdx.x;                       // t*B + b
    int v = texts[row];
    const float* src = emb + (size_t)v * EE;
    float* dst = g_x + (size_t)row * EE;
    for (int e = threadIdx.x; e < EE; e += blockDim.x) dst[e] = src[e];
}

// ---------------- C[M,1536] = A[M,K] @ W[1536,K]^T + bias  (tf32 mma) ----------------
// BM=128, BN=128, BK=16, register double-buffered global->smem pipeline.
__global__ void __launch_bounds__(256)
gemm_tf32_kernel(const float* __restrict__ W,
                 const float* __restrict__ bias,
                 int K, int useA1) {
    __shared__ float As[16][136];
    __shared__ float Bs[16][136];
    const float* A = useA1 ? g_h1 : g_x;
    float* C = g_xp;
    const int tid = threadIdx.x;
    const int bm = blockIdx.x * 128;
    const int bn = blockIdx.y * 128;
    const int warp = tid >> 5, lane = tid & 31;
    const int wm = warp >> 1, wn = warp & 1;
    const int m0 = wm * 32, n0 = wn * 64;
    const int r = lane >> 2, c = lane & 3;

    float acc[2][8][4];
#pragma unroll
    for (int mt = 0; mt < 2; mt++)
#pragma unroll
        for (int nt = 0; nt < 8; nt++)
#pragma unroll
            for (int q = 0; q < 4; q++) acc[mt][nt][q] = 0.f;

    const int lrow = tid & 127;
    const int lk = (tid >> 7) * 8;

    float va[8], vb[8];

    auto load_tiles = [&](int k0) {
        const float* ap = A + (size_t)(bm + lrow) * K + k0 + lk;
        const float* wp = W + (size_t)(bn + lrow) * K + k0 + lk;
        if (k0 + lk + 7 < K) {
            float4 p = *(const float4*)ap;
            float4 q4 = *(const float4*)(ap + 4);
            va[0]=p.x; va[1]=p.y; va[2]=p.z; va[3]=p.w;
            va[4]=q4.x; va[5]=q4.y; va[6]=q4.z; va[7]=q4.w;
            p = *(const float4*)wp;
            q4 = *(const float4*)(wp + 4);
            vb[0]=p.x; vb[1]=p.y; vb[2]=p.z; vb[3]=p.w;
            vb[4]=q4.x; vb[5]=q4.y; vb[6]=q4.z; vb[7]=q4.w;
        } else {
#pragma unroll
            for (int q = 0; q < 8; q++) {
                int k = k0 + lk + q;
                va[q] = (k < K) ? ap[q] : 0.f;
                vb[q] = (k < K) ? wp[q] : 0.f;
            }
        }
    };
    auto store_tiles = [&]() {
#pragma unroll
        for (int q = 0; q < 8; q++) {
            As[lk + q][lrow] = __uint_as_float(cvt_tf32(va[q]));
            Bs[lk + q][lrow] = __uint_as_float(cvt_tf32(vb[q]));
        }
    };
    auto compute = [&]() {
#pragma unroll
        for (int ks = 0; ks < 16; ks += 8) {
            uint32_t af[2][4], bf[8][2];
#pragma unroll
            for (int mt = 0; mt < 2; mt++) {
                int mm = m0 + mt * 16;
                af[mt][0] = __float_as_uint(As[ks + c][mm + r]);
                af[mt][1] = __float_as_uint(As[ks + c][mm + r + 8]);
                af[mt][2] = __float_as_uint(As[ks + c + 4][mm + r]);
                af[mt][3] = __float_as_uint(As[ks + c + 4][mm + r + 8]);
            }
#pragma unroll
            for (int nt = 0; nt < 8; nt++) {
                int nn = n0 + nt * 8 + r;
                bf[nt][0] = __float_as_uint(Bs[ks + c][nn]);
                bf[nt][1] = __float_as_uint(Bs[ks + c + 4][nn]);
            }
#pragma unroll
            for (int mt = 0; mt < 2; mt++)
#pragma unroll
                for (int nt = 0; nt < 8; nt++) {
                    asm volatile(
                        "mma.sync.aligned.m16n8k8.row.col.f32.tf32.tf32.f32 "
                        "{%0,%1,%2,%3}, {%4,%5,%6,%7}, {%8,%9}, {%0,%1,%2,%3};\n"
                        : "+f"(acc[mt][nt][0]), "+f"(acc[mt][nt][1]),
                          "+f"(acc[mt][nt][2]), "+f"(acc[mt][nt][3])
                        : "r"(af[mt][0]), "r"(af[mt][1]), "r"(af[mt][2]), "r"(af[mt][3]),
                          "r"(bf[nt][0]), "r"(bf[nt][1]));
                }
        }
    };

    load_tiles(0);
    store_tiles();
    __syncthreads();
    for (int k0 = 16; k0 < K; k0 += 16) {
        load_tiles(k0);       // prefetch next tile (LDGs overlap mma below)
        compute();
        __syncthreads();
        store_tiles();
        __syncthreads();
    }
    compute();

#pragma unroll
    for (int mt = 0; mt < 2; mt++) {
        int mrow = bm + m0 + mt * 16 + r;
#pragma unroll
        for (int nt = 0; nt < 8; nt++) {
            int col = bn + n0 + nt * 8 + 2 * c;
            float b0 = bias[col], b1 = bias[col + 1];
            float2 o0, o1;
            o0.x = acc[mt][nt][0] + b0; o0.y = acc[mt][nt][1] + b1;
            o1.x = acc[mt][nt][2] + b0; o1.y = acc[mt][nt][3] + b1;
            *(float2*)&C[(size_t)mrow * G3 + col] = o0;
            *(float2*)&C[(size_t)(mrow + 8) * G3 + col] = o1;
        }
    }
}

// ---------------- persistent GRU recurrence (fp16 mma, W as A-operand) ----------------
__device__ __forceinline__ float sigmoidf_(float x) { return 1.f / (1.f + __expf(-x)); }

#define HEP 520   // hsm (fp16) row stride in halves: conflict-free
#define GSP 52    // gsm row stride in floats: conflict-free C-frag stores

__global__ void __launch_bounds__(256, 1)
gru_kernel(const float* __restrict__ Whh,
           const float* __restrict__ bhh,
           int layer) {
    __shared__ __half hsm[16 * HEP];   // h[t] for our 16 batches, fp16
    __shared__ float  gsm[16 * GSP];   // recurrent gate pre-activations [batch][gateCol]
    __shared__ float  bsm[48];

    const float* xp = g_xp;
    float* hout = layer ? g_h2 : g_h1;

    const int tid = threadIdx.x;
    const int warp = tid >> 5;
    const int lane = tid & 31;
    const int bs = blockIdx.x & 3;
    const int js = blockIdx.x >> 2;
    const int b0 = bs * 16, j0 = js * 16;

    if (tid < 48) {
        int g = tid >> 4, j = tid & 15;
        bsm[tid] = bhh[g * 512 + j0 + j];
    }

    // ---- load W A-fragments into fp16x2 registers (warps 0-5) ----
    const int r = lane >> 2, c = lane & 3;
    const int mtile = warp >> 1, wn = warp & 1;
    uint32_t wa0[32], wa1[32], wa2[32], wa3[32];
    if (warp < 6) {
        const float* rowa = Whh + (size_t)(mtile * 512 + j0 + r) * 512;
        const float* rowb = Whh + (size_t)(mtile * 512 + j0 + r + 8) * 512;
#pragma unroll
        for (int ks = 0; ks < 32; ks++) {
            int k = ks * 16 + 2 * c;
            float2 p0 = *(const float2*)(rowa + k);
            float2 p1 = *(const float2*)(rowb + k);
            float2 p2 = *(const float2*)(rowa + k + 8);
            float2 p3 = *(const float2*)(rowb + k + 8);
            wa0[ks] = pack_f16x2(p0.x, p0.y);
            wa1[ks] = pack_f16x2(p1.x, p1.y);
            wa2[ks] = pack_f16x2(p2.x, p2.y);
            wa3[ks] = pack_f16x2(p3.x, p3.y);
        }
    }

    for (int idx = tid; idx < 16 * HEP / 2; idx += 256)
        ((uint32_t*)hsm)[idx] = 0u;     // h0 = 0
    __syncthreads();

    const int gb = tid >> 4, gj = tid & 15;
    const float br = bsm[gj], bz = bsm[16 + gj], bn_ = bsm[32 + gj];
    float hprev = 0.f;

    const __half* hrow = hsm + (wn * 8 + r) * HEP;

    for (int t = 0; t < TT; t++) {
        const float* xpt = xp + ((size_t)t * BB + b0 + gb) * G3 + j0 + gj;
        float xr = xpt[0], xz = xpt[512], xn = xpt[1024];

        if (warp < 6) {
            float ac[4][4];
#pragma unroll
            for (int g4 = 0; g4 < 4; g4++)
#pragma unroll
                for (int q = 0; q < 4; q++) ac[g4][q] = 0.f;
#pragma unroll
            for (int ks = 0; ks < 32; ks += 4) {
#pragma unroll
                for (int g4 = 0; g4 < 4; g4++) {
                    int k = (ks + g4) * 16 + 2 * c;
                    uint32_t bfr0 = *(const uint32_t*)(hrow + k);
                    uint32_t bfr1 = *(const uint32_t*)(hrow + k + 8);
                    asm volatile(
                        "mma.sync.aligned.m16n8k16.row.col.f32.f16.f16.f32 "
                        "{%0,%1,%2,%3}, {%4,%5,%6,%7}, {%8,%9}, {%0,%1,%2,%3};\n"
                        : "+f"(ac[g4][0]), "+f"(ac[g4][1]),
                          "+f"(ac[g4][2]), "+f"(ac[g4][3])
                        : "r"(wa0[ks + g4]), "r"(wa1[ks + g4]),
                          "r"(wa2[ks + g4]), "r"(wa3[ks + g4]),
                          "r"(bfr0), "r"(bfr1));
                }
            }
            float d0 = (ac[0][0] + ac[1][0]) + (ac[2][0] + ac[3][0]);
            float d1 = (ac[0][1] + ac[1][1]) + (ac[2][1] + ac[3][1]);
            float d2 = (ac[0][2] + ac[1][2]) + (ac[2][2] + ac[3][2]);
            float d3 = (ac[0][3] + ac[1][3]) + (ac[2][3] + ac[3][3]);
            int bb0 = wn * 8 + 2 * c;
            int gc0 = mtile * 16 + r;
            gsm[bb0 * GSP + gc0]           = d0;
            gsm[(bb0 + 1) * GSP + gc0]     = d1;
            gsm[bb0 * GSP + gc0 + 8]       = d2;
            gsm[(bb0 + 1) * GSP + gc0 + 8] = d3;
        }
        __syncthreads();

        {
            float ar = gsm[gb * GSP + gj];
            float az = gsm[gb * GSP + 16 + gj];
            float an = gsm[gb * GSP + 32 + gj];
            float rr = sigmoidf_(xr + ar + br);
            float zz = sigmoidf_(xz + az + bz);
            float nn = tanhf(xn + rr * (an + bn_));
            float hnew = (1.f - zz) * nn + zz * hprev;
            hprev = hnew;
            size_t orow = (size_t)t * BB + b0 + gb;
            hout[orow * HH + j0 + gj] = hnew;                       // fp32 (downstream)
            g_hex[orow * HH + j0 + gj] = __float2half_rn(hnew);     // fp16 (exchange)
        }

        if (t == TT - 1) break;

        // ---- flag-array group barrier: parallel release stores + parallel poll ----
        __syncthreads();                 // all h stores done CTA-wide
        int* fl = &g_flag[layer][t][bs][0];
        if (tid == 0)
            asm volatile("st.release.gpu.global.s32 [%0], 1;" :: "l"(fl + js) : "memory");
        if (warp == 0) {
            const int* fp = fl + lane;   // each lane watches one peer CTA
            int v;
            do {
                asm volatile("ld.acquire.gpu.global.s32 %0, [%1];"
                             : "=r"(v) : "l"(fp) : "memory");
            } while (__all_sync(0xffffffffu, v) == 0);
        }
        __syncthreads();

        // ---- reload full fp16 h[t] for our 16 batches (16 KB), batched for MLP ----
        {
            const __half* src = g_hex + ((size_t)t * BB + b0) * HH;
            uint4 vv[4];
#pragma unroll
            for (int q = 0; q < 4; q++) {
                int idx = tid + q * 256;
                int bb = idx >> 6, ch = idx & 63;
                vv[q] = *(const uint4*)(src + (size_t)bb * HH + ch * 8);
            }
#pragma unroll
            for (int q = 0; q < 4; q++) {
                int idx = tid + q * 256;
                int bb = idx >> 6, ch = idx & 63;
                *(uint4*)(hsm + bb * HEP + ch * 8) = vv[q];
            }
        }
        __syncthreads();
    }
}

// ---------------- mean pool over batch + FC ----------------
__global__ void pool_fc_kernel(const float* __restrict__ fcW,
                               const float* __restrict__ fcb,
                               float* __restrict__ out) {
    __shared__ float pooled[HH];
    int t = blockIdx.x;
    const float* base = g_h2 + (size_t)t * BB * HH;
    for (int h = threadIdx.x; h < HH; h += blockDim.x) {
        float s = 0.f;
        for (int b = 0; b < BB; b++) s += base[b * HH + h];
        pooled[h] = s * (1.f / 64.f);
    }
    __syncthreads();
    int w = threadIdx.x >> 5, lane = threadIdx.x & 31;
    if (w < LL) {
        float s = 0.f;
        for (int h = lane; h < HH; h += 32) s = fmaf(pooled[h], fcW[w * HH + h], s);
#pragma unroll
        for (int o = 16; o > 0; o >>= 1) s += __shfl_xor_sync(0xffffffffu, s, o);
        if (lane == 0) out[t * LL + w] = s + fcb[w];
    }
}

// ---------------- launch ----------------
extern "C" void kernel_launch(void* const* d_in, const int* in_sizes, int n_in,
                              void* d_out, int out_size) {
    (void)in_sizes; (void)n_in; (void)out_size;
    const int*   texts = (const int*)d_in[0];
    const float* emb   = (const float*)d_in[1];
    const float* Wih0  = (const float*)d_in[2];
    const float* Whh0  = (const float*)d_in[3];
    const float* bih0  = (const float*)d_in[4];
    const float* bhh0  = (const float*)d_in[5];
    const float* Wih1  = (const float*)d_in[6];
    const float* Whh1  = (const float*)d_in[7];
    const float* bih1  = (const float*)d_in[8];
    const float* bhh1  = (const float*)d_in[9];
    const float* fcW   = (const float*)d_in[10];
    const float* fcb   = (const float*)d_in[11];
    float* out = (float*)d_out;

    zero_bar_kernel<<<512, 256>>>();     // zero all 131072 flags
    embed_kernel<<<TB, 128>>>(texts, emb);

    dim3 ggrid(TB / 128, G3 / 128);
    gemm_tf32_kernel<<<ggrid, 256>>>(Wih0, bih0, EE, 0);   // xp0 from g_x
    gru_kernel<<<128, 256>>>(Whh0, bhh0, 0);               // -> g_h1
    gemm_tf32_kernel<<<ggrid, 256>>>(Wih1, bih1, HH, 1);   // xp1 from g_h1
    gru_kernel<<<128, 256>>>(Whh1, bhh1, 1);               // -> g_h2
    pool_fc_kernel<<<TT, 256>>>(fcW, fcb, out);
}